// round 3
// baseline (speedup 1.0000x reference)
#include <cuda_runtime.h>
#include <math.h>

// ---------------------------------------------------------------------------
// GATEdgeNet: 2x GATConv (single head) + edge MLP, fp32 throughout.
//
// Pipeline:
//   CSR build (by dst, over symmetrized edges + self loops)
//   h1 = x @ W_g1              (SGEMM 50000x64x128)
//   s1/t1 = h1 . a1_src/a1_dst
//   f1 = relu(GAT-aggregate(h1) + b_g1)          [warp-per-node gather]
//   h2 = f1 @ W_g2             (SGEMM 50000x128x64)
//   s2/t2 ...
//   xf[:,64:] = relu(GAT-aggregate(h2) + b_g2);  xf[:,:64] = x
//   U = xf @ W_m1[0:128]; V = xf @ W_m1[128:256] (SGEMM x2)
//   out[e] = sigmoid( relu(U[row]+V[col]+d@W_d+b1) . W_m2 + b2 )
// ---------------------------------------------------------------------------

constexpr int NN = 50000;
constexpr int NE = 800000;
constexpr int ET = 2 * NE + NN;   // 1,650,000

// ---- scratch (static device allocations; no runtime alloc allowed) --------
__device__ float g_h1[NN * 128];
__device__ float g_f1[NN * 128];
__device__ float g_h2[NN * 64];
__device__ float g_xf[NN * 128];
__device__ float g_U[NN * 128];
__device__ float g_V[NN * 128];
__device__ float g_s1[NN];
__device__ float g_t1[NN];
__device__ float g_s2[NN];
__device__ float g_t2[NN];
__device__ int   g_deg[NN];
__device__ int   g_rowptr[NN + 1];
__device__ int   g_cursor[NN];
__device__ int   g_adj[ET];
__device__ float g_ebuf[ET];

// ---------------------------------------------------------------------------
__device__ __forceinline__ void edge_sd(int t, const int* __restrict__ ei,
                                        int& src, int& dst) {
    if (t < NE) {            // forward copy:  src=row, dst=col
        src = ei[2 * t];
        dst = ei[2 * t + 1];
    } else if (t < 2 * NE) { // reversed copy: src=col, dst=row
        int u = t - NE;
        src = ei[2 * u + 1];
        dst = ei[2 * u];
    } else {                 // self loop
        src = dst = t - 2 * NE;
    }
}

__global__ void k_zero_deg() {
    for (int i = blockIdx.x * blockDim.x + threadIdx.x; i < NN;
         i += gridDim.x * blockDim.x)
        g_deg[i] = 0;
}

__global__ void k_hist(const int* __restrict__ ei) {
    for (int t = blockIdx.x * blockDim.x + threadIdx.x; t < ET;
         t += gridDim.x * blockDim.x) {
        int s, d;
        edge_sd(t, ei, s, d);
        atomicAdd(&g_deg[d], 1);
    }
}

// single-block scan over 50000 degrees -> rowptr (exclusive) + cursor copy
__global__ void k_scan() {
    __shared__ int sh[1024];
    const int tid = threadIdx.x;
    if (tid == 0) g_rowptr[0] = 0;
    const int nchunk = (NN + 1023) / 1024;
    int running = 0;
    for (int c = 0; c < nchunk; c++) {
        int i = c * 1024 + tid;
        int v = (i < NN) ? g_deg[i] : 0;
        sh[tid] = v;
        __syncthreads();
        #pragma unroll
        for (int off = 1; off < 1024; off <<= 1) {
            int t2 = (tid >= off) ? sh[tid - off] : 0;
            __syncthreads();
            sh[tid] += t2;
            __syncthreads();
        }
        int inc = sh[tid];
        int tot = sh[1023];
        if (i < NN) {
            g_rowptr[i + 1] = running + inc;       // exclusive prefix at i+1
            g_cursor[i]     = running + inc - v;   // exclusive prefix at i
        }
        running += tot;
        __syncthreads();
    }
}

__global__ void k_fill(const int* __restrict__ ei) {
    for (int t = blockIdx.x * blockDim.x + threadIdx.x; t < ET;
         t += gridDim.x * blockDim.x) {
        int s, d;
        edge_sd(t, ei, s, d);
        int pos = atomicAdd(&g_cursor[d], 1);
        g_adj[pos] = s;
    }
}

__global__ void k_copyx(const float* __restrict__ x) {
    const int total = NN * 16;  // 16 float4 per row of 64
    for (int i = blockIdx.x * blockDim.x + threadIdx.x; i < total;
         i += gridDim.x * blockDim.x) {
        int n = i >> 4, q = i & 15;
        *reinterpret_cast<float4*>(g_xf + (size_t)n * 128 + q * 4) =
            reinterpret_cast<const float4*>(x)[i];
    }
}

// ---------------------------------------------------------------------------
// SGEMM: C[M x BN] = A[M x K] * B[K x BN], row-major, K % 8 == 0, N == BN.
// 128 x BN block tile, 256 threads, 8 x (BN/16) register tile.
// ---------------------------------------------------------------------------
template <int BN>
__global__ void __launch_bounds__(256)
k_sgemm(const float* __restrict__ A, const float* __restrict__ B,
        float* __restrict__ C, int M, int K) {
    constexpr int BM = 128, BK = 8, TN = BN / 16;
    __shared__ float As[BK][BM];
    __shared__ float Bs[BK][BN];

    const int tid = threadIdx.x;
    const int bm  = blockIdx.x * BM;
    const int tx  = tid & 15;    // 16 col groups
    const int ty  = tid >> 4;    // 16 row groups of 8

    float acc[8][TN];
    #pragma unroll
    for (int i = 0; i < 8; i++)
        #pragma unroll
        for (int j = 0; j < TN; j++) acc[i][j] = 0.f;

    const int a_m = tid >> 1;
    const int a_k = (tid & 1) * 4;
    int a_row = bm + a_m;
    if (a_row >= M) a_row = M - 1;   // clamp: bogus rows never stored
    const float* Aptr = A + (size_t)a_row * K + a_k;

    for (int k0 = 0; k0 < K; k0 += BK) {
        float4 av = *reinterpret_cast<const float4*>(Aptr + k0);
        As[a_k + 0][a_m] = av.x;
        As[a_k + 1][a_m] = av.y;
        As[a_k + 2][a_m] = av.z;
        As[a_k + 3][a_m] = av.w;
        if (BN == 128) {
            int bk = tid >> 5, bn = (tid & 31) << 2;
            *reinterpret_cast<float4*>(&Bs[bk][bn]) =
                *reinterpret_cast<const float4*>(B + (size_t)(k0 + bk) * BN + bn);
        } else {
            if (tid < 128) {
                int bk = tid >> 4, bn = (tid & 15) << 2;
                *reinterpret_cast<float4*>(&Bs[bk][bn]) =
                    *reinterpret_cast<const float4*>(B + (size_t)(k0 + bk) * BN + bn);
            }
        }
        __syncthreads();

        #pragma unroll
        for (int k = 0; k < BK; k++) {
            float ra[8];
            {
                float4 r0 = *reinterpret_cast<const float4*>(&As[k][ty * 8]);
                float4 r1 = *reinterpret_cast<const float4*>(&As[k][ty * 8 + 4]);
                ra[0] = r0.x; ra[1] = r0.y; ra[2] = r0.z; ra[3] = r0.w;
                ra[4] = r1.x; ra[5] = r1.y; ra[6] = r1.z; ra[7] = r1.w;
            }
            float rb[TN];
            #pragma unroll
            for (int jj = 0; jj < TN; jj += 4) {
                float4 q = *reinterpret_cast<const float4*>(&Bs[k][tx * TN + jj]);
                rb[jj] = q.x; rb[jj + 1] = q.y; rb[jj + 2] = q.z; rb[jj + 3] = q.w;
            }
            #pragma unroll
            for (int i = 0; i < 8; i++)
                #pragma unroll
                for (int j = 0; j < TN; j++)
                    acc[i][j] = fmaf(ra[i], rb[j], acc[i][j]);
        }
        __syncthreads();
    }

    #pragma unroll
    for (int i = 0; i < 8; i++) {
        int row = bm + ty * 8 + i;
        if (row < M) {
            float* cp = C + (size_t)row * BN + tx * TN;
            #pragma unroll
            for (int j = 0; j < TN; j += 4) {
                float4 o = make_float4(acc[i][j], acc[i][j + 1],
                                       acc[i][j + 2], acc[i][j + 3]);
                *reinterpret_cast<float4*>(cp + j) = o;
            }
        }
    }
}

// ---------------------------------------------------------------------------
// per-row dots: s[i] = h[i].a_src, t[i] = h[i].a_dst   (warp per row)
// ---------------------------------------------------------------------------
template <int C>
__global__ void k_rowdots(const float* __restrict__ h,
                          const float* __restrict__ asrc,
                          const float* __restrict__ adst,
                          float* __restrict__ s, float* __restrict__ t) {
    int w = (blockIdx.x * blockDim.x + threadIdx.x) >> 5;
    int lane = threadIdx.x & 31;
    if (w >= NN) return;
    const float* hr = h + (size_t)w * C;
    float ds = 0.f, dt = 0.f;
    #pragma unroll
    for (int c = lane; c < C; c += 32) {
        float v = hr[c];
        ds = fmaf(v, __ldg(asrc + c), ds);
        dt = fmaf(v, __ldg(adst + c), dt);
    }
    #pragma unroll
    for (int o = 16; o; o >>= 1) {
        ds += __shfl_xor_sync(0xffffffffu, ds, o);
        dt += __shfl_xor_sync(0xffffffffu, dt, o);
    }
    if (lane == 0) { s[w] = ds; t[w] = dt; }
}

// ---------------------------------------------------------------------------
// GAT aggregation, warp per dst node (gather over CSR; no value atomics).
//   out[n, ocoloff + c] = relu( (sum_j w_j h[src_j, c]) / (sum_j w_j + 1e-16)
//                               + bias[c] )
//   w_j = exp(e_j - max), e_j = leaky_relu(s[src_j] + t[n], 0.2)
// ---------------------------------------------------------------------------
template <int C>
__global__ void k_gatagg(const float* __restrict__ h,
                         const float* __restrict__ s,
                         const float* __restrict__ t,
                         const float* __restrict__ bias,
                         float* __restrict__ out, int ostride, int ocoloff) {
    constexpr int CPL = C / 32;
    int w = (blockIdx.x * blockDim.x + threadIdx.x) >> 5;
    int lane = threadIdx.x & 31;
    if (w >= NN) return;

    const int beg = g_rowptr[w];
    const int end = g_rowptr[w + 1];
    const float tn = t[w];

    // pass 1: e + segment max (every lane reads back only its own writes)
    float m = -3.0e38f;
    for (int j = beg + lane; j < end; j += 32) {
        float e = s[g_adj[j]] + tn;
        e = (e >= 0.f) ? e : 0.2f * e;
        g_ebuf[j] = e;
        m = fmaxf(m, e);
    }
    #pragma unroll
    for (int o = 16; o; o >>= 1)
        m = fmaxf(m, __shfl_xor_sync(0xffffffffu, m, o));

    // pass 2: weighted accumulate
    float denom = 0.f;
    float acc[CPL];
    #pragma unroll
    for (int q = 0; q < CPL; q++) acc[q] = 0.f;

    for (int j0 = beg; j0 < end; j0 += 32) {
        int j = j0 + lane;
        float wv = 0.f;
        int sj = 0;
        if (j < end) {
            wv = __expf(g_ebuf[j] - m);
            sj = g_adj[j];
        }
        denom += wv;
        int cnt = end - j0;
        if (cnt > 32) cnt = 32;
        for (int k = 0; k < cnt; k++) {
            float wk = __shfl_sync(0xffffffffu, wv, k);
            int   sk = __shfl_sync(0xffffffffu, sj, k);
            if (CPL == 4) {
                float4 hv = *reinterpret_cast<const float4*>(
                    h + (size_t)sk * C + lane * 4);
                acc[0] = fmaf(wk, hv.x, acc[0]);
                acc[1] = fmaf(wk, hv.y, acc[1]);
                acc[2] = fmaf(wk, hv.z, acc[2]);
                acc[3] = fmaf(wk, hv.w, acc[3]);
            } else {
                float2 hv = *reinterpret_cast<const float2*>(
                    h + (size_t)sk * C + lane * 2);
                acc[0] = fmaf(wk, hv.x, acc[0]);
                acc[1] = fmaf(wk, hv.y, acc[1]);
            }
        }
    }
    #pragma unroll
    for (int o = 16; o; o >>= 1)
        denom += __shfl_xor_sync(0xffffffffu, denom, o);

    const float inv = 1.f / (denom + 1e-16f);
    float* op = out + (size_t)w * ostride + ocoloff + lane * CPL;
    if (CPL == 4) {
        float4 r;
        r.x = fmaxf(acc[0] * inv + __ldg(bias + lane * 4 + 0), 0.f);
        r.y = fmaxf(acc[1] * inv + __ldg(bias + lane * 4 + 1), 0.f);
        r.z = fmaxf(acc[2] * inv + __ldg(bias + lane * 4 + 2), 0.f);
        r.w = fmaxf(acc[3] * inv + __ldg(bias + lane * 4 + 3), 0.f);
        *reinterpret_cast<float4*>(op) = r;
    } else {
        float2 r;
        r.x = fmaxf(acc[0] * inv + __ldg(bias + lane * 2 + 0), 0.f);
        r.y = fmaxf(acc[1] * inv + __ldg(bias + lane * 2 + 1), 0.f);
        *reinterpret_cast<float2*>(op) = r;
    }
}

// ---------------------------------------------------------------------------
// Edge MLP: warp per edge.
//   out[e] = sigmoid( relu(U[row]+V[col]+d@W_d+b1) . W_m2 + b2 )
// ---------------------------------------------------------------------------
__global__ void __launch_bounds__(256)
k_edgemlp(const int* __restrict__ ei, const float* __restrict__ ed,
          const float* __restrict__ Wm1, const float* __restrict__ b1,
          const float* __restrict__ Wm2, const float* __restrict__ b2,
          float* __restrict__ out) {
    __shared__ float sWd[16 * 128];
    __shared__ float sB1[128];
    __shared__ float sW2[128];
    const int tid = threadIdx.x;
    for (int i = tid; i < 16 * 128; i += 256)
        sWd[i] = Wm1[256 * 128 + i];       // rows 256..271 of W_m1 (contiguous)
    if (tid < 128) {
        sB1[tid] = b1[tid];
        sW2[tid] = Wm2[tid];
    }
    __syncthreads();

    const int e = blockIdx.x * 8 + (tid >> 5);
    const int lane = tid & 31;
    if (e >= NE) return;

    const int row = ei[2 * e];
    const int col = ei[2 * e + 1];

    float4 u = *reinterpret_cast<const float4*>(g_U + (size_t)row * 128 + lane * 4);
    float4 v = *reinterpret_cast<const float4*>(g_V + (size_t)col * 128 + lane * 4);
    float4 bb = *reinterpret_cast<const float4*>(sB1 + lane * 4);
    float a0 = u.x + v.x + bb.x;
    float a1 = u.y + v.y + bb.y;
    float a2 = u.z + v.z + bb.z;
    float a3 = u.w + v.w + bb.w;

    const float4* dp = reinterpret_cast<const float4*>(ed + (size_t)e * 16);
    float4 d0 = dp[0], d1 = dp[1], d2 = dp[2], d3 = dp[3];
    float dv[16] = {d0.x, d0.y, d0.z, d0.w, d1.x, d1.y, d1.z, d1.w,
                    d2.x, d2.y, d2.z, d2.w, d3.x, d3.y, d3.z, d3.w};
    #pragma unroll
    for (int k = 0; k < 16; k++) {
        float4 wv = *reinterpret_cast<const float4*>(sWd + k * 128 + lane * 4);
        a0 = fmaf(dv[k], wv.x, a0);
        a1 = fmaf(dv[k], wv.y, a1);
        a2 = fmaf(dv[k], wv.z, a2);
        a3 = fmaf(dv[k], wv.w, a3);
    }
    a0 = fmaxf(a0, 0.f); a1 = fmaxf(a1, 0.f);
    a2 = fmaxf(a2, 0.f); a3 = fmaxf(a3, 0.f);

    float4 w2 = *reinterpret_cast<const float4*>(sW2 + lane * 4);
    float p = a0 * w2.x + a1 * w2.y + a2 * w2.z + a3 * w2.w;
    #pragma unroll
    for (int o = 16; o; o >>= 1)
        p += __shfl_xor_sync(0xffffffffu, p, o);

    if (lane == 0) {
        float z = p + __ldg(b2);
        out[e] = 1.f / (1.f + __expf(-z));
    }
}

// ---------------------------------------------------------------------------
extern "C" void kernel_launch(void* const* d_in, const int* in_sizes, int n_in,
                              void* d_out, int out_size) {
    const float* x    = (const float*)d_in[0];
    const int*   ei   = (const int*)  d_in[1];
    const float* ed   = (const float*)d_in[2];
    const float* Wg1  = (const float*)d_in[3];
    const float* a1s  = (const float*)d_in[4];
    const float* a1d  = (const float*)d_in[5];
    const float* bg1  = (const float*)d_in[6];
    const float* Wg2  = (const float*)d_in[7];
    const float* a2s  = (const float*)d_in[8];
    const float* a2d  = (const float*)d_in[9];
    const float* bg2  = (const float*)d_in[10];
    const float* Wm1  = (const float*)d_in[11];
    const float* bm1  = (const float*)d_in[12];
    const float* Wm2  = (const float*)d_in[13];
    const float* bm2  = (const float*)d_in[14];
    float* out = (float*)d_out;

    float *h1, *f1, *h2, *xf, *U, *V, *s1, *t1, *s2, *t2;
    cudaGetSymbolAddress((void**)&h1, g_h1);
    cudaGetSymbolAddress((void**)&f1, g_f1);
    cudaGetSymbolAddress((void**)&h2, g_h2);
    cudaGetSymbolAddress((void**)&xf, g_xf);
    cudaGetSymbolAddress((void**)&U,  g_U);
    cudaGetSymbolAddress((void**)&V,  g_V);
    cudaGetSymbolAddress((void**)&s1, g_s1);
    cudaGetSymbolAddress((void**)&t1, g_t1);
    cudaGetSymbolAddress((void**)&s2, g_s2);
    cudaGetSymbolAddress((void**)&t2, g_t2);

    const int warpBlocks = (NN * 32 + 255) / 256;   // 6250
    const int gemmBlocks = (NN + 127) / 128;        // 391

    // CSR build (dst-sorted adjacency, shared by both GAT layers)
    k_zero_deg<<<128, 256>>>();
    k_copyx<<<1024, 256>>>(x);
    k_hist<<<2048, 256>>>(ei);
    k_scan<<<1, 1024>>>();
    k_fill<<<2048, 256>>>(ei);

    // GAT layer 1
    k_sgemm<128><<<gemmBlocks, 256>>>(x, Wg1, h1, NN, 64);
    k_rowdots<128><<<warpBlocks, 256>>>(h1, a1s, a1d, s1, t1);
    k_gatagg<128><<<warpBlocks, 256>>>(h1, s1, t1, bg1, f1, 128, 0);

    // GAT layer 2 (writes into right half of xf)
    k_sgemm<64><<<gemmBlocks, 256>>>(f1, Wg2, h2, NN, 128);
    k_rowdots<64><<<warpBlocks, 256>>>(h2, a2s, a2d, s2, t2);
    k_gatagg<64><<<warpBlocks, 256>>>(h2, s2, t2, bg2, xf, 128, 64);

    // Edge MLP, factored: U = xf @ Wm1[0:128], V = xf @ Wm1[128:256]
    k_sgemm<128><<<gemmBlocks, 256>>>(xf, Wm1, U, NN, 128);
    k_sgemm<128><<<gemmBlocks, 256>>>(xf, Wm1 + 128 * 128, V, NN, 128);
    k_edgemlp<<<NE / 8, 256>>>(ei, ed, Wm1, bm1, Wm2, bm2, out);
}